// round 17
// baseline (speedup 1.0000x reference)
#include <cuda_runtime.h>

// Problem constants: NP=44 tiny MLPs, B=400000 batch.
#define NP_  44
#define B_   400000
#define B4_  (B_ / 4)          // 100000 float4 per l  (= 32 * 3125)
#define TPB  160               // 5 warps
#define VPT  5                 // float4s in flight per iteration
#define ITER 5                 // iterations per block
#define STEP (TPB * VPT)       // 800 float4 per iteration
#define CHUNK (STEP * ITER)    // 4000 float4 per block; 100000/4000 = 25 exact

// Converged design at the LTS roofline: 140.8 MB compulsory traffic at the
// ~6300 B/cyc full-chip L2 ceiling -> ~20 us kernel floor (measured 7.0 TB/s).
// Math: input is scalar per element, so the 1->4->8->4->1 ReLU MLP collapses
// to out = (x>0 ? s_pos[l] : s_neg[l]) * x (ReLU masks depend only on
// sign(x)). Streaming cache policy both directions; software-pipelined inner
// loop keeps 5 loads in flight across each store burst.
__global__ __launch_bounds__(TPB, 10) void fused_mlp_stream(
    const float4* __restrict__ X, float4* __restrict__ O,
    const float* __restrict__ w1,   // (NP,4,1)
    const float* __restrict__ w2,   // (NP,8,4)
    const float* __restrict__ w3,   // (NP,4,8)
    const float* __restrict__ w4) { // (NP,1,4)

    __shared__ float sw[72];        // [0:4) w1, [4:36) w2, [36:68) w3, [68:72) w4
    __shared__ float s_scale[2];

    const int l = blockIdx.y;
    const int t = threadIdx.x;

    // Parallel weight fetch (lanes 0..71, one load each).
    if (t < 72) {
        float v;
        if      (t < 4)  v = w1[l * 4  + t];
        else if (t < 36) v = w2[l * 32 + (t - 4)];
        else if (t < 68) v = w3[l * 32 + (t - 36)];
        else             v = w4[l * 4  + (t - 68)];
        sw[t] = v;
    }
    __syncthreads();

    // Two threads compute the two collapsed scalars (t=0: x>0, t=1: x<0).
    if (t < 2) {
        const bool pos = (t == 0);
        const float* W1 = sw;
        const float* W2 = sw + 4;
        const float* W3 = sw + 36;
        const float* W4 = sw + 68;
        float a[4];
        #pragma unroll
        for (int i = 0; i < 4; ++i) {
            float w = W1[i];
            a[i] = (pos ? (w > 0.0f) : (w < 0.0f)) ? w : 0.0f;
        }
        float b[8];
        #pragma unroll
        for (int j = 0; j < 8; ++j) {
            float s = 0.0f;
            #pragma unroll
            for (int i = 0; i < 4; ++i) s += W2[j * 4 + i] * a[i];
            b[j] = (pos ? (s > 0.0f) : (s < 0.0f)) ? s : 0.0f;
        }
        float c[4];
        #pragma unroll
        for (int i = 0; i < 4; ++i) {
            float s = 0.0f;
            #pragma unroll
            for (int j = 0; j < 8; ++j) s += W3[i * 8 + j] * b[j];
            c[i] = (pos ? (s > 0.0f) : (s < 0.0f)) ? s : 0.0f;
        }
        float out = 0.0f;
        #pragma unroll
        for (int i = 0; i < 4; ++i) out += W4[i] * c[i];
        s_scale[t] = out;
    }
    __syncthreads();

    const float sp = s_scale[0];
    const float sn = s_scale[1];

    // Base of this block's exact 4000-float4 region within its l.
    const float4* __restrict__ xi = X + (long)l * B4_ + blockIdx.x * CHUNK + t;
    float4*       __restrict__ oi = O + (long)l * B4_ + blockIdx.x * CHUNK + t;

    // Software pipeline: prologue loads iter 0; each steady-state step issues
    // iter it+1's loads BEFORE iter it's stores so 5 loads stay in flight
    // across every store burst.
    float4 cur[VPT], nxt[VPT];
    #pragma unroll
    for (int k = 0; k < VPT; ++k)
        cur[k] = __ldcs(&xi[k * TPB]);

    #pragma unroll
    for (int it = 0; it < ITER; ++it) {
        if (it + 1 < ITER) {
            const float4* xn = xi + STEP;
            #pragma unroll
            for (int k = 0; k < VPT; ++k)
                nxt[k] = __ldcs(&xn[k * TPB]);
        }
        #pragma unroll
        for (int k = 0; k < VPT; ++k) {
            float4 v = cur[k];
            float4 o;
            o.x = (v.x > 0.0f ? sp : sn) * v.x;
            o.y = (v.y > 0.0f ? sp : sn) * v.y;
            o.z = (v.z > 0.0f ? sp : sn) * v.z;
            o.w = (v.w > 0.0f ? sp : sn) * v.w;
            __stcs(&oi[k * TPB], o);
        }
        #pragma unroll
        for (int k = 0; k < VPT; ++k)
            cur[k] = nxt[k];
        xi += STEP;
        oi += STEP;
    }
}

extern "C" void kernel_launch(void* const* d_in, const int* in_sizes, int n_in,
                              void* d_out, int out_size) {
    const float* X  = (const float*)d_in[0];
    const float* w1 = (const float*)d_in[1];
    const float* w2 = (const float*)d_in[2];
    const float* w3 = (const float*)d_in[3];
    const float* w4 = (const float*)d_in[4];
    float* out = (float*)d_out;

    dim3 grid(B4_ / CHUNK, NP_);   // (25, 44) = 1100 blocks, exact
    fused_mlp_stream<<<grid, TPB>>>((const float4*)X, (float4*)out,
                                    w1, w2, w3, w4);
}